// round 1
// baseline (speedup 1.0000x reference)
#include <cuda_runtime.h>
#include <cstdint>
#include <cstddef>

// SDDMM: out[M,N] = x[M,N] * (y[M,K] @ z[K,N]),  M=N=8192, K=64, fp32.
// Fused single pass: per-CTA 128x128 tile, whole K=64 staged in SMEM once,
// tf32 warp MMA (m16n8k8), epilogue multiplies by x and streams out.

#define M_DIM 8192
#define N_DIM 8192
#define K_DIM 64

#define BM 128
#define BN 128
#define YS 68    // smem row stride (words) for y tile: (4r+c)%32 conflict-free
#define ZS 136   // smem row stride (words) for z tile: (8r+c)%32 conflict-free

#define SMEM_WORDS (BM * YS + K_DIM * ZS)
#define SMEM_BYTES (SMEM_WORDS * 4)

__device__ __forceinline__ uint32_t f2tf32(float f) {
    uint32_t r;
    asm("cvt.rna.tf32.f32 %0, %1;" : "=r"(r) : "f"(f));
    return r;
}

__global__ void __launch_bounds__(256, 2)
sddmm_tf32_kernel(const float* __restrict__ x,
                  const float* __restrict__ y,
                  const float* __restrict__ z,
                  float* __restrict__ out)
{
    extern __shared__ uint32_t smem[];
    uint32_t* ys = smem;             // [BM][YS] tf32 bits
    uint32_t* zs = smem + BM * YS;   // [K_DIM][ZS] tf32 bits

    const int bm = blockIdx.y;
    const int bn = blockIdx.x;
    const int tid = threadIdx.x;

    // ---- Stage y tile [128 x 64] (row-major, contiguous block of y) ----
    {
        const float4* yg = reinterpret_cast<const float4*>(y + (size_t)bm * BM * K_DIM);
        #pragma unroll
        for (int i = 0; i < (BM * K_DIM / 4) / 256; i++) {
            int idx = tid + i * 256;            // float4 index
            float4 v = yg[idx];
            int r = idx >> 4;                   // 16 float4 per row
            int c = (idx & 15) << 2;
            uint32_t* p = ys + r * YS + c;
            p[0] = f2tf32(v.x); p[1] = f2tf32(v.y);
            p[2] = f2tf32(v.z); p[3] = f2tf32(v.w);
        }
    }
    // ---- Stage z tile [64 x 128] (row stride N_DIM) ----
    {
        #pragma unroll
        for (int i = 0; i < (K_DIM * BN / 4) / 256; i++) {
            int idx = tid + i * 256;            // float4 index
            int r = idx >> 5;                   // 32 float4 per row
            int c = (idx & 31) << 2;
            float4 v = *reinterpret_cast<const float4*>(
                z + (size_t)r * N_DIM + (size_t)bn * BN + c);
            uint32_t* p = zs + r * ZS + c;
            p[0] = f2tf32(v.x); p[1] = f2tf32(v.y);
            p[2] = f2tf32(v.z); p[3] = f2tf32(v.w);
        }
    }
    __syncthreads();

    const int warp = tid >> 5;
    const int lane = tid & 31;
    const int wm = (warp >> 1) * 32;   // warp rows base: 4 warps over M
    const int wn = (warp & 1) * 64;    // warp cols base: 2 warps over N
    const int g  = lane >> 2;          // groupID 0..7
    const int ti = lane & 3;           // thread-in-group 0..3

    float acc[2][8][4];
    #pragma unroll
    for (int a = 0; a < 2; a++)
        #pragma unroll
        for (int b = 0; b < 8; b++)
            #pragma unroll
            for (int q = 0; q < 4; q++) acc[a][b][q] = 0.f;

    #pragma unroll
    for (int ks = 0; ks < K_DIM / 8; ks++) {
        uint32_t A[2][4];
        #pragma unroll
        for (int mt = 0; mt < 2; mt++) {
            const uint32_t* base = ys + (wm + mt * 16 + g) * YS + ks * 8 + ti;
            A[mt][0] = base[0];
            A[mt][1] = base[8 * YS];
            A[mt][2] = base[4];
            A[mt][3] = base[8 * YS + 4];
        }
        uint32_t B[8][2];
        #pragma unroll
        for (int nt = 0; nt < 8; nt++) {
            const uint32_t* base = zs + (ks * 8 + ti) * ZS + wn + nt * 8 + g;
            B[nt][0] = base[0];
            B[nt][1] = base[4 * ZS];
        }
        #pragma unroll
        for (int mt = 0; mt < 2; mt++)
            #pragma unroll
            for (int nt = 0; nt < 8; nt++)
                asm volatile(
                    "mma.sync.aligned.m16n8k8.row.col.f32.tf32.tf32.f32 "
                    "{%0,%1,%2,%3}, {%4,%5,%6,%7}, {%8,%9}, {%0,%1,%2,%3};"
                    : "+f"(acc[mt][nt][0]), "+f"(acc[mt][nt][1]),
                      "+f"(acc[mt][nt][2]), "+f"(acc[mt][nt][3])
                    : "r"(A[mt][0]), "r"(A[mt][1]), "r"(A[mt][2]), "r"(A[mt][3]),
                      "r"(B[nt][0]), "r"(B[nt][1]));
    }

    // ---- Epilogue: out = x * acc, fragment-coordinate addressed float2 IO ----
    const size_t rowbase = (size_t)(bm * BM + wm + g);
    const int    colbase = bn * BN + wn + 2 * ti;
    #pragma unroll
    for (int mt = 0; mt < 2; mt++) {
        const size_t r0 = rowbase + mt * 16;
        #pragma unroll
        for (int nt = 0; nt < 8; nt++) {
            const int cc = colbase + nt * 8;
            {
                const float2 xv = *reinterpret_cast<const float2*>(x + r0 * N_DIM + cc);
                float2 o;
                o.x = xv.x * acc[mt][nt][0];
                o.y = xv.y * acc[mt][nt][1];
                *reinterpret_cast<float2*>(out + r0 * N_DIM + cc) = o;
            }
            {
                const float2 xv = *reinterpret_cast<const float2*>(x + (r0 + 8) * N_DIM + cc);
                float2 o;
                o.x = xv.x * acc[mt][nt][2];
                o.y = xv.y * acc[mt][nt][3];
                *reinterpret_cast<float2*>(out + (r0 + 8) * N_DIM + cc) = o;
            }
        }
    }
}

extern "C" void kernel_launch(void* const* d_in, const int* in_sizes, int n_in,
                              void* d_out, int out_size)
{
    const float* x = (const float*)d_in[0];
    const float* y = (const float*)d_in[1];
    const float* z = (const float*)d_in[2];
    float* out = (float*)d_out;
    (void)in_sizes; (void)n_in; (void)out_size;

    cudaFuncSetAttribute(sddmm_tf32_kernel,
                         cudaFuncAttributeMaxDynamicSharedMemorySize, SMEM_BYTES);

    dim3 grid(N_DIM / BN, M_DIM / BM);
    sddmm_tf32_kernel<<<grid, 256, SMEM_BYTES>>>(x, y, z, out);
}

// round 2
// speedup vs baseline: 1.1621x; 1.1621x over previous
#include <cuda_runtime.h>
#include <cstdint>
#include <cstddef>

// SDDMM: out[M,N] = x[M,N] * (y[M,K] @ z[K,N]),  M=N=8192, K=64, fp32.
// Fused single pass: per-CTA 128x128 tile, whole K=64 staged in SMEM once,
// tf32 warp MMA (m16n8k8). Epilogue transposes accumulators through SMEM
// (reusing the staging buffer) so x-loads and out-stores are fully coalesced
// float4 row-major accesses.

#define M_DIM 8192
#define N_DIM 8192
#define K_DIM 64

#define BM 128
#define BN 128
#define YS 68    // smem row stride (words) for y tile
#define ZS 136   // smem row stride (words) for z tile

#define SMEM_WORDS (BM * YS + K_DIM * ZS)   // 17408 words
#define SMEM_BYTES (SMEM_WORDS * 4)         // 69632 B

#define EPS 68   // epilogue smem row stride (words); 8 warps * 32 * 68 = 17408

__device__ __forceinline__ uint32_t f2tf32(float f) {
    uint32_t r;
    asm("cvt.rna.tf32.f32 %0, %1;" : "=r"(r) : "f"(f));
    return r;
}

__global__ void __launch_bounds__(256, 2)
sddmm_tf32_kernel(const float* __restrict__ x,
                  const float* __restrict__ y,
                  const float* __restrict__ z,
                  float* __restrict__ out)
{
    extern __shared__ uint32_t smem[];
    uint32_t* ys = smem;             // [BM][YS] tf32 bits
    uint32_t* zs = smem + BM * YS;   // [K_DIM][ZS] tf32 bits

    const int bm = blockIdx.y;
    const int bn = blockIdx.x;
    const int tid = threadIdx.x;

    // ---- Stage y tile [128 x 64] (row-major, contiguous block of y) ----
    {
        const float4* yg = reinterpret_cast<const float4*>(y + (size_t)bm * BM * K_DIM);
        #pragma unroll
        for (int i = 0; i < (BM * K_DIM / 4) / 256; i++) {
            int idx = tid + i * 256;            // float4 index
            float4 v = yg[idx];
            int r = idx >> 4;                   // 16 float4 per row
            int c = (idx & 15) << 2;
            uint32_t* p = ys + r * YS + c;
            p[0] = f2tf32(v.x); p[1] = f2tf32(v.y);
            p[2] = f2tf32(v.z); p[3] = f2tf32(v.w);
        }
    }
    // ---- Stage z tile [64 x 128] (row stride N_DIM) ----
    {
        #pragma unroll
        for (int i = 0; i < (K_DIM * BN / 4) / 256; i++) {
            int idx = tid + i * 256;            // float4 index
            int r = idx >> 5;                   // 32 float4 per row
            int c = (idx & 31) << 2;
            float4 v = *reinterpret_cast<const float4*>(
                z + (size_t)r * N_DIM + (size_t)bn * BN + c);
            uint32_t* p = zs + r * ZS + c;
            p[0] = f2tf32(v.x); p[1] = f2tf32(v.y);
            p[2] = f2tf32(v.z); p[3] = f2tf32(v.w);
        }
    }
    __syncthreads();

    const int warp = tid >> 5;
    const int lane = tid & 31;
    const int wm = (warp >> 1) * 32;   // warp rows base: 4 warps over M
    const int wn = (warp & 1) * 64;    // warp cols base: 2 warps over N
    const int g  = lane >> 2;          // groupID 0..7
    const int ti = lane & 3;           // thread-in-group 0..3

    float acc[2][8][4];
    #pragma unroll
    for (int a = 0; a < 2; a++)
        #pragma unroll
        for (int b = 0; b < 8; b++)
            #pragma unroll
            for (int q = 0; q < 4; q++) acc[a][b][q] = 0.f;

    #pragma unroll
    for (int ks = 0; ks < K_DIM / 8; ks++) {
        uint32_t A[2][4];
        #pragma unroll
        for (int mt = 0; mt < 2; mt++) {
            const uint32_t* base = ys + (wm + mt * 16 + g) * YS + ks * 8 + ti;
            A[mt][0] = base[0];
            A[mt][1] = base[8 * YS];
            A[mt][2] = base[4];
            A[mt][3] = base[8 * YS + 4];
        }
        uint32_t B[8][2];
        #pragma unroll
        for (int nt = 0; nt < 8; nt++) {
            const uint32_t* base = zs + (ks * 8 + ti) * ZS + wn + nt * 8 + g;
            B[nt][0] = base[0];
            B[nt][1] = base[4 * ZS];
        }
        #pragma unroll
        for (int mt = 0; mt < 2; mt++)
            #pragma unroll
            for (int nt = 0; nt < 8; nt++)
                asm volatile(
                    "mma.sync.aligned.m16n8k8.row.col.f32.tf32.tf32.f32 "
                    "{%0,%1,%2,%3}, {%4,%5,%6,%7}, {%8,%9}, {%0,%1,%2,%3};"
                    : "+f"(acc[mt][nt][0]), "+f"(acc[mt][nt][1]),
                      "+f"(acc[mt][nt][2]), "+f"(acc[mt][nt][3])
                    : "r"(A[mt][0]), "r"(A[mt][1]), "r"(A[mt][2]), "r"(A[mt][3]),
                      "r"(B[nt][0]), "r"(B[nt][1]));
    }

    // All warps done reading y/z staging; reuse the buffer for the epilogue.
    __syncthreads();

    // ---- Epilogue: transpose acc through warp-private SMEM, then fully
    //      coalesced float4 x-load / multiply / out-store.
    // Warp region: 32 rows x 64 cols, stride EPS=68 words.
    // Column swizzle: physical col = (logical col + 4*(row&3)) & 63
    //   -> STS.64 (fragment side) and LDS.128 (row side) both bank-conflict-free.
    float* ep = reinterpret_cast<float*>(smem) + warp * (32 * EPS);

    #pragma unroll
    for (int mt = 0; mt < 2; mt++) {
        #pragma unroll
        for (int half = 0; half < 2; half++) {
            const int lr = mt * 16 + half * 8 + g;     // local row 0..31
            const int sw = 4 * (lr & 3);
            float* rowp = ep + lr * EPS;
            #pragma unroll
            for (int nt = 0; nt < 8; nt++) {
                const int lc = (nt * 8 + 2 * ti + sw) & 63;
                float2 v;
                v.x = acc[mt][nt][2 * half + 0];
                v.y = acc[mt][nt][2 * half + 1];
                *reinterpret_cast<float2*>(rowp + lc) = v;
            }
        }
    }
    __syncwarp();

    // Row-major readout: 2 rows per iteration, 16 lanes per row, float4 each.
    const int sub  = lane >> 4;           // 0..1: which of the 2 rows
    const int c4   = (lane & 15) << 2;    // float4 col within 64
    const size_t grow_base = (size_t)(bm * BM + wm);
    const int    gcol      = bn * BN + wn + c4;

    #pragma unroll
    for (int it = 0; it < 16; it++) {
        const int lr = it * 2 + sub;
        const int pc = (c4 + 4 * (lr & 3)) & 63;
        const float4 a = *reinterpret_cast<const float4*>(ep + lr * EPS + pc);
        const size_t goff = (grow_base + lr) * (size_t)N_DIM + gcol;
        const float4 xv = *reinterpret_cast<const float4*>(x + goff);
        float4 o;
        o.x = xv.x * a.x;
        o.y = xv.y * a.y;
        o.z = xv.z * a.z;
        o.w = xv.w * a.w;
        *reinterpret_cast<float4*>(out + goff) = o;
    }
}

extern "C" void kernel_launch(void* const* d_in, const int* in_sizes, int n_in,
                              void* d_out, int out_size)
{
    const float* x = (const float*)d_in[0];
    const float* y = (const float*)d_in[1];
    const float* z = (const float*)d_in[2];
    float* out = (float*)d_out;
    (void)in_sizes; (void)n_in; (void)out_size;

    cudaFuncSetAttribute(sddmm_tf32_kernel,
                         cudaFuncAttributeMaxDynamicSharedMemorySize, SMEM_BYTES);

    dim3 grid(N_DIM / BN, M_DIM / BM);
    sddmm_tf32_kernel<<<grid, 256, SMEM_BYTES>>>(x, y, z, out);
}